// round 17
// baseline (speedup 1.0000x reference)
#include <cuda_runtime.h>
#include <cuda_bf16.h>

#define B_  8192
#define T_  200
#define IN_ 4
#define H_  16
#define L_  4
#define MLP_IN  (H_ * T_)   // 3200
#define MLP_HID 64
#define MLP_OUT 28

typedef unsigned long long ull;

// ---------------- scratch (no allocations allowed) ----------------
// hid partials as f32x2 (even-k, odd-k) halves: [j][b]
__device__ ull g_hid[MLP_HID * B_];    // 4 MB

// ---------------- packed f32x2 helpers ----------------
__device__ __forceinline__ ull pack2(float lo, float hi) {
    ull r; asm("mov.b64 %0, {%1, %2};" : "=l"(r) : "f"(lo), "f"(hi)); return r;
}
__device__ __forceinline__ void unpack2(ull v, float& lo, float& hi) {
    asm("mov.b64 {%0, %1}, %2;" : "=f"(lo), "=f"(hi) : "l"(v));
}
__device__ __forceinline__ ull ffma2(ull a, ull b, ull c) {
    ull d; asm("fma.rn.f32x2 %0, %1, %2, %3;" : "=l"(d) : "l"(a), "l"(b), "l"(c)); return d;
}

// ---------------- activations via MUFU.TANH (1 MUFU each) ------------
__device__ __forceinline__ float tanh_hw(float x) {
    float y; asm("tanh.approx.f32 %0, %1;" : "=f"(y) : "f"(x)); return y;
}
__device__ __forceinline__ float sigmoid_hw(float x) {
    return fmaf(tanh_hw(0.5f * x), 0.5f, 0.5f);
}

// h ring: float hbuf[parity(2)][layer(4)][step(2)][eg(8)][row 20]
#define HB_STEP 160
#define HB_L2   (2 * HB_STEP)
#define HB_PAR2 (4 * HB_L2)
#define HB_TOTAL (2 * HB_PAR2)          // 2560 floats
// x: float xbuf[parity(2)][eg(8)][8] : floats 0-3 = x(t0), 4-7 = x(t0+1)
#define XB_PAR  64
#define XB_TOTAL (2 * XB_PAR)

// paired weight layouts (ulonglong2 = 4 consecutive k as two f32x2 pairs)
#define WINP_N  (L_ * 4 * 4 * 16)   // input-projection, all gates (16 KB)
#define WRECP_N (L_ * 2 * 4 * 16)   // recurrent, gates 2..3       (8 KB)
#define BIASP_N (L_ * 2 * 16)       // bias pairs                  (2 KB)

// =====================================================================
// Layer-pipelined LSTM with FUSED MLP phase 1.
// CTA = 4 warps = 4 layers, 8 batch elems; two timesteps per barrier
// interval. Additionally, every interval all 4 warps accumulate the
// W1 @ h3 partial for the two h3 steps produced in the PREVIOUS
// interval (read from hbuf slot 3, q parity): warp wid owns
// j = wid*16 + sub; accumulators (f32x2 even/odd-k halves) in smem.
// W1 (819 KB) streams through L2, broadcast across CTAs.
// regs <= 128 -> 4 CTAs/SM. 1024 CTAs x 128 threads.
// =====================================================================
__global__ void __launch_bounds__(128, 4) lstm_kernel(
    const float* __restrict__ x,         // [B, T, IN]
    const float* __restrict__ Wih0,      // [64, 4]
    const float* __restrict__ Wih_rest,  // [3, 64, 16]
    const float* __restrict__ Whh,       // [4, 64, 16]
    const float* __restrict__ bih,       // [4, 64]
    const float* __restrict__ bhh,       // [4, 64]
    const float* __restrict__ W1)        // [64, 3200]
{
    __shared__ __align__(16) float hbuf[HB_TOTAL];
    __shared__ __align__(16) float xbuf[XB_TOTAL];
    __shared__ __align__(16) ulonglong2 WinP[WINP_N];
    __shared__ __align__(16) ulonglong2 WrecP[WRECP_N];
    __shared__ __align__(16) ulonglong2 biasP2[BIASP_N];
    __shared__ __align__(16) ull hidS[8 * MLP_HID];   // [e(8)][j(64)] f32x2 halves

    const int wid  = threadIdx.x >> 5;
    const int lane = threadIdx.x & 31;
    const int sub  = lane & 15;
    const int grp  = lane >> 4;
    const int l    = (wid + (int)blockIdx.x) & 3;        // layer rotation
    const int b0c  = (int)blockIdx.x * 8;                // CTA batch base
    const int b0   = b0c + grp * 4;                      // elems b0..b0+3
    const int jj   = wid * 16 + sub;                     // owned MLP j

    for (int i = threadIdx.x; i < HB_TOTAL; i += blockDim.x) hbuf[i] = 0.0f;
    for (int i = threadIdx.x; i < XB_TOTAL; i += blockDim.x) xbuf[i] = 0.0f;
    for (int i = threadIdx.x; i < 8 * MLP_HID; i += blockDim.x) hidS[i] = 0ull;

    // ---- stage WinP ----
    for (int idx = threadIdx.x; idx < WINP_N; idx += blockDim.x) {
        int j  = idx & 15;
        int kc = (idx >> 4) & 3;
        int g  = (idx >> 6) & 3;
        int li = idx >> 8;
        float4 v = make_float4(0.f, 0.f, 0.f, 0.f);
        if (li == 0) {
            if (kc == 0) v = *reinterpret_cast<const float4*>(Wih0 + (g * 16 + j) * IN_);
        } else {
            v = *reinterpret_cast<const float4*>(
                Wih_rest + (li - 1) * 1024 + (g * 16 + j) * 16 + kc * 4);
        }
        WinP[idx] = *reinterpret_cast<ulonglong2*>(&v);
    }
    // ---- stage WrecP (gates 2..3) ----
    for (int idx = threadIdx.x; idx < WRECP_N; idx += blockDim.x) {
        int j  = idx & 15;
        int kc = (idx >> 4) & 3;
        int gp = (idx >> 6) & 1;
        int li = idx >> 7;
        float4 v = *reinterpret_cast<const float4*>(
            Whh + li * 1024 + ((gp + 2) * 16 + j) * 16 + kc * 4);
        WrecP[idx] = *reinterpret_cast<ulonglong2*>(&v);
    }
    // ---- stage biasP2 ----
    for (int idx = threadIdx.x; idx < BIASP_N; idx += blockDim.x) {
        int j  = idx & 15;
        int gp = (idx >> 4) & 1;
        int li = idx >> 5;
        ulonglong2 v;
        v.x = pack2(bih[li * 64 + (2 * gp + 0) * 16 + j] + bhh[li * 64 + (2 * gp + 0) * 16 + j], 0.0f);
        v.y = pack2(bih[li * 64 + (2 * gp + 1) * 16 + j] + bhh[li * 64 + (2 * gp + 1) * 16 + j], 0.0f);
        biasP2[idx] = v;
    }

    // ---- gates 0..1 recurrent weights into registers ----
    ull Wrec[2][8];   // [gate][kpair]
#pragma unroll
    for (int g = 0; g < 2; ++g) {
        const float* rsrc = Whh + l * 1024 + (g * 16 + sub) * 16;
#pragma unroll
        for (int kc = 0; kc < 4; ++kc) {
            ulonglong2 v = *reinterpret_cast<const ulonglong2*>(rsrc + kc * 4);
            Wrec[g][2 * kc] = v.x; Wrec[g][2 * kc + 1] = v.y;
        }
    }

    // initial x(0), x(1) into xbuf parity 1 (interval 0 reads 1-p = 1)
    if (threadIdx.x < 8) {
        float4 v0 = *reinterpret_cast<const float4*>(x + (long)(b0c + threadIdx.x) * (T_ * IN_));
        float4 v1 = *reinterpret_cast<const float4*>(x + (long)(b0c + threadIdx.x) * (T_ * IN_) + IN_);
        *reinterpret_cast<float4*>(xbuf + XB_PAR + threadIdx.x * 8)     = v0;
        *reinterpret_cast<float4*>(xbuf + XB_PAR + threadIdx.x * 8 + 4) = v1;
    }

    float c_own[4] = {0.0f, 0.0f, 0.0f, 0.0f};
    const ulonglong2* const winL  = WinP  + (l * 4) * 4 * 16;  // [g][kc][j]
    const ulonglong2* const wrecL = WrecP + (l * 2) * 4 * 16;  // [gp][kc][j]
    const ulonglong2* const biasL = biasP2 + (l * 2) * 16;     // [gp][j]
    __syncthreads();

    const int NI = T_ / 2 + L_ - 1;   // 103 layer intervals; +1 MLP drain
    for (int i = 0; i <= NI; ++i) {
        const int p = i & 1;
        const int q = 1 - p;
        const int t0 = 2 * (i - l);
        const bool active = (i >= l) && (t0 < T_);

        if (active) {
            // warp 0 prefetches x(t0+2), x(t0+3) for next interval
            if (l == 0 && lane < 8 && t0 + 2 < T_) {
                const float* xsrcg = x + (long)(b0c + lane) * (T_ * IN_) + (t0 + 2) * IN_;
                float4 v0 = *reinterpret_cast<const float4*>(xsrcg);
                float4 v1 = *reinterpret_cast<const float4*>(xsrcg + IN_);
                *reinterpret_cast<float4*>(xbuf + p * XB_PAR + lane * 8)     = v0;
                *reinterpret_cast<float4*>(xbuf + p * XB_PAR + lane * 8 + 4) = v1;
            }

#pragma unroll
            for (int s = 0; s < 2; ++s) {
                ull acc[4][4];   // [gate][e], halves = (even-k, odd-k)
                {
                    ulonglong2 b01 = biasL[0 * 16 + sub];
                    ulonglong2 b23 = biasL[1 * 16 + sub];
#pragma unroll
                    for (int e = 0; e < 4; ++e) {
                        acc[0][e] = b01.x; acc[1][e] = b01.y;
                        acc[2][e] = b23.x; acc[3][e] = b23.y;
                    }
                }

                // ---- input projection ----
                if (l == 0) {
                    const float* xsrc = xbuf + q * XB_PAR + s * 4;
#pragma unroll
                    for (int e = 0; e < 4; ++e) {
                        ulonglong2 xv = *reinterpret_cast<const ulonglong2*>(
                            xsrc + (grp * 4 + e) * 8);
#pragma unroll
                        for (int g = 0; g < 4; ++g) {
                            ulonglong2 wv = winL[(g * 4 + 0) * 16 + sub];
                            acc[g][e] = ffma2(wv.x, xv.x, acc[g][e]);
                            acc[g][e] = ffma2(wv.y, xv.y, acc[g][e]);
                        }
                    }
                } else {
                    const float* hsrc = hbuf + q * HB_PAR2 + (l - 1) * HB_L2 + s * HB_STEP;
#pragma unroll
                    for (int kc = 0; kc < 4; ++kc) {
                        ulonglong2 hv[4];
#pragma unroll
                        for (int e = 0; e < 4; ++e)
                            hv[e] = *reinterpret_cast<const ulonglong2*>(
                                hsrc + (grp * 4 + e) * 20 + kc * 4);
#pragma unroll
                        for (int g = 0; g < 4; ++g) {
                            ulonglong2 wv = winL[(g * 4 + kc) * 16 + sub];
#pragma unroll
                            for (int e = 0; e < 4; ++e) {
                                acc[g][e] = ffma2(wv.x, hv[e].x, acc[g][e]);
                                acc[g][e] = ffma2(wv.y, hv[e].y, acc[g][e]);
                            }
                        }
                    }
                }

                // ---- recurrent projection ----
                {
                    // s=0: own layer step1 of prev interval; s=1: own step0
                    const float* hsrc = (s == 0)
                        ? hbuf + q * HB_PAR2 + l * HB_L2 + 1 * HB_STEP
                        : hbuf + p * HB_PAR2 + l * HB_L2 + 0 * HB_STEP;
#pragma unroll
                    for (int kc = 0; kc < 4; ++kc) {
                        ulonglong2 hv[4];
#pragma unroll
                        for (int e = 0; e < 4; ++e)
                            hv[e] = *reinterpret_cast<const ulonglong2*>(
                                hsrc + (grp * 4 + e) * 20 + kc * 4);
#pragma unroll
                        for (int g = 0; g < 2; ++g)
#pragma unroll
                            for (int e = 0; e < 4; ++e) {
                                acc[g][e] = ffma2(Wrec[g][2 * kc],     hv[e].x, acc[g][e]);
                                acc[g][e] = ffma2(Wrec[g][2 * kc + 1], hv[e].y, acc[g][e]);
                            }
#pragma unroll
                        for (int gp = 0; gp < 2; ++gp) {
                            ulonglong2 wv = wrecL[(gp * 4 + kc) * 16 + sub];
#pragma unroll
                            for (int e = 0; e < 4; ++e) {
                                acc[gp + 2][e] = ffma2(wv.x, hv[e].x, acc[gp + 2][e]);
                                acc[gp + 2][e] = ffma2(wv.y, hv[e].y, acc[gp + 2][e]);
                            }
                        }
                    }
                }

                // ---- horizontal add + activations + state update ----
                float hn[4];
#pragma unroll
                for (int e = 0; e < 4; ++e) {
                    float lo, hi, ai, af, ag, ao;
                    unpack2(acc[0][e], lo, hi); ai = lo + hi;
                    unpack2(acc[1][e], lo, hi); af = lo + hi;
                    unpack2(acc[2][e], lo, hi); ag = lo + hi;
                    unpack2(acc[3][e], lo, hi); ao = lo + hi;
                    float iv = sigmoid_hw(ai);
                    float fv = sigmoid_hw(af);
                    float gv = tanh_hw(ag);
                    float ov = sigmoid_hw(ao);
                    float cv = fmaf(fv, c_own[e], iv * gv);
                    c_own[e] = cv;
                    hn[e] = ov * tanh_hw(cv);
                }

                // ---- publish new h into [p][l][s] ----
                __syncwarp();
                {
                    float* hdst = hbuf + p * HB_PAR2 + l * HB_L2 + s * HB_STEP;
#pragma unroll
                    for (int e = 0; e < 4; ++e)
                        hdst[(grp * 4 + e) * 20 + sub] = hn[e];
                }
                __syncwarp();
            }
        }

        // ---- fused MLP1: accumulate W1 @ h3 for steps of interval i-1 ----
        // h3(t = 2i-8, 2i-7) sits in hbuf[q][3][0..1], written at i-1.
        if (i >= 4) {
            const int tb = 2 * i - 8;
            ull a[4];
#pragma unroll
            for (int e = 0; e < 4; ++e) a[e] = hidS[(grp * 4 + e) * MLP_HID + jj];
#pragma unroll
            for (int s = 0; s < 2; ++s) {
                const float* w1r = W1 + (long)jj * MLP_IN + (tb + s) * 16;
                ulonglong2 wq0 = *reinterpret_cast<const ulonglong2*>(w1r + 0);
                ulonglong2 wq1 = *reinterpret_cast<const ulonglong2*>(w1r + 4);
                ulonglong2 wq2 = *reinterpret_cast<const ulonglong2*>(w1r + 8);
                ulonglong2 wq3 = *reinterpret_cast<const ulonglong2*>(w1r + 12);
                const float* hsrc = hbuf + q * HB_PAR2 + 3 * HB_L2 + s * HB_STEP;
#pragma unroll
                for (int e = 0; e < 4; ++e) {
                    const float* hr = hsrc + (grp * 4 + e) * 20;
                    ulonglong2 h0 = *reinterpret_cast<const ulonglong2*>(hr + 0);
                    ulonglong2 h1 = *reinterpret_cast<const ulonglong2*>(hr + 4);
                    ulonglong2 h2 = *reinterpret_cast<const ulonglong2*>(hr + 8);
                    ulonglong2 h3 = *reinterpret_cast<const ulonglong2*>(hr + 12);
                    a[e] = ffma2(wq0.x, h0.x, a[e]); a[e] = ffma2(wq0.y, h0.y, a[e]);
                    a[e] = ffma2(wq1.x, h1.x, a[e]); a[e] = ffma2(wq1.y, h1.y, a[e]);
                    a[e] = ffma2(wq2.x, h2.x, a[e]); a[e] = ffma2(wq2.y, h2.y, a[e]);
                    a[e] = ffma2(wq3.x, h3.x, a[e]); a[e] = ffma2(wq3.y, h3.y, a[e]);
                }
            }
#pragma unroll
            for (int e = 0; e < 4; ++e) hidS[(grp * 4 + e) * MLP_HID + jj] = a[e];
        }

        __syncthreads();
    }

    // ---- write hid partials (f32x2 halves) to global [j][b] ----
#pragma unroll
    for (int e = 0; e < 4; ++e)
        g_hid[(long)jj * B_ + b0 + e] = hidS[(grp * 4 + e) * MLP_HID + jj];
}

// =====================================================================
// MLP phase 2: horizontal-add halves, +b1, relu, W2, write out [B, 28].
// =====================================================================
__global__ void __launch_bounds__(128) mlp2_kernel(
    const float* __restrict__ W2,   // [28, 64]
    const float* __restrict__ b1,   // [64]
    const float* __restrict__ b2,   // [28]
    float* __restrict__ out)        // [B, 28]
{
    __shared__ float W2s[MLP_OUT * MLP_HID];
    __shared__ float b1s[MLP_HID];
    __shared__ float b2s[MLP_OUT];
    for (int idx = threadIdx.x; idx < MLP_OUT * MLP_HID; idx += blockDim.x)
        W2s[idx] = W2[idx];
    if (threadIdx.x < MLP_HID) b1s[threadIdx.x] = b1[threadIdx.x];
    if (threadIdx.x < MLP_OUT) b2s[threadIdx.x] = b2[threadIdx.x];
    __syncthreads();

    const int b = blockIdx.x * 128 + threadIdx.x;
    float hid[MLP_HID];
#pragma unroll
    for (int j = 0; j < MLP_HID; ++j) {
        float lo, hi;
        unpack2(g_hid[(long)j * B_ + b], lo, hi);
        hid[j] = fmaxf(lo + hi + b1s[j], 0.0f);
    }
#pragma unroll
    for (int o = 0; o < MLP_OUT; ++o) {
        float a = b2s[o];
#pragma unroll
        for (int j = 0; j < MLP_HID; ++j)
            a = fmaf(hid[j], W2s[o * MLP_HID + j], a);
        out[(long)b * MLP_OUT + o] = a;
    }
}

// =====================================================================
extern "C" void kernel_launch(void* const* d_in, const int* in_sizes, int n_in,
                              void* d_out, int out_size)
{
    const float* x        = (const float*)d_in[0];
    const float* Wih0     = (const float*)d_in[1];
    const float* Wih_rest = (const float*)d_in[2];
    const float* Whh      = (const float*)d_in[3];
    const float* bih      = (const float*)d_in[4];
    const float* bhh      = (const float*)d_in[5];
    const float* W1       = (const float*)d_in[6];
    const float* b1       = (const float*)d_in[7];
    const float* W2       = (const float*)d_in[8];
    const float* b2       = (const float*)d_in[9];
    float* out = (float*)d_out;

    lstm_kernel<<<1024, 128>>>(x, Wih0, Wih_rest, Whh, bih, bhh, W1);
    mlp2_kernel<<<64, 128>>>(W2, b1, b2, out);
}